// round 12
// baseline (speedup 1.0000x reference)
#include <cuda_runtime.h>
#include <cuda_bf16.h>
#include <float.h>

// Problem-size upper bounds (from reference setup_inputs)
#define MAXN 50000
#define MAXE 800000
#define MAXET (MAXE + MAXN)   // + self loops

// ---------------- device scratch --------------------------------------------
__device__ float g_hfeat[MAXN * 64];
__device__ float g_hlin [MAXN * 64];
__device__ float g_esrc [MAXN];
__device__ float g_edst [MAXN];
__device__ float g_ew   [MAXET];
__device__ int   g_hist [MAXN];
__device__ int   g_off  [MAXN + 1];
__device__ int   g_cursor[MAXN];
__device__ int   g_srcs [MAXET];

// ---------------- helpers ---------------------------------------------------
__device__ __forceinline__ float gat_warp_sum(float v) {
#pragma unroll
    for (int o = 16; o; o >>= 1) v += __shfl_xor_sync(0xffffffffu, v, o);
    return v;
}
__device__ __forceinline__ float gat_warp_max(float v) {
#pragma unroll
    for (int o = 16; o; o >>= 1) v = fmaxf(v, __shfl_xor_sync(0xffffffffu, v, o));
    return v;
}

// ---------------- edge sorting (counting sort by dst) -----------------------
// edge_index is int32 [2, E] row-major: ei[i] = src, ei[E+i] = dst.
__global__ void gat_hist_kernel(const int* __restrict__ ei, int E, int n) {
    int i = blockIdx.x * blockDim.x + threadIdx.x;
    int total = E + n;
    if (i >= total) return;
    int d = (i < E) ? ei[E + i] : (i - E);
    if ((unsigned)d >= (unsigned)n) return;
    atomicAdd(&g_hist[d], 1);
}

// single-block scan; SELF-ZEROES g_hist after consuming it so the next graph
// replay starts from a clean histogram (first run relies on static zero-init).
__global__ void gat_scan_kernel(int n) {
    __shared__ int partial[1024];
    int t = threadIdx.x;
    int chunk = (n + 1023) / 1024;
    int begin = t * chunk;
    int endi  = min(begin + chunk, n);
    int sum = 0;
    for (int i = begin; i < endi; i++) sum += g_hist[i];
    partial[t] = sum;
    __syncthreads();
#pragma unroll
    for (int d = 1; d < 1024; d <<= 1) {
        int v = (t >= d) ? partial[t - d] : 0;
        __syncthreads();
        partial[t] += v;
        __syncthreads();
    }
    int run = (t == 0) ? 0 : partial[t - 1];
    for (int i = begin; i < endi; i++) {
        int h = g_hist[i];
        g_off[i]    = run;
        g_cursor[i] = run;
        run += h;
        g_hist[i] = 0;           // ready for next replay
    }
    if (t == 0) g_off[n] = partial[1023];
}

__global__ void gat_scatter_kernel(const int* __restrict__ ei, int E, int n) {
    int i = blockIdx.x * blockDim.x + threadIdx.x;
    int total = E + n;
    if (i >= total) return;
    int s, d;
    if (i < E) { s = ei[i]; d = ei[E + i]; }
    else       { s = d = i - E; }
    if ((unsigned)d >= (unsigned)n || (unsigned)s >= (unsigned)n) return;
    int pos = atomicAdd(&g_cursor[d], 1);
    g_srcs[pos] = s;
}

// ---------------- tiled GEMM: out = X @ W^T (+bias), optional e_src/e_dst ---
// Block = 256 threads, tile = 32 rows x FOUT cols. NO x smem staging: each
// warp owns rows {rg+8i} exclusively, so x rows are read as broadcast
// LDG.128 directly (each element touched exactly once; RPT independent
// loads batched per k4-iter hide L2 latency). Only W lives in smem
// (c-major, float4 XOR swizzle -> conflict-free).
// SRCSEL: 0 = param X, 1 = g_hfeat.   DSTSEL: 0 = g_hfeat, 1 = g_hlin.
template <int FIN, int FOUT, bool BIAS, bool COMPE, int SRCSEL, int DSTSEL>
__global__ void gat_gemm_kernel(const float* __restrict__ Xparam,
                                const float* __restrict__ W,
                                const float* __restrict__ bias,
                                const float* __restrict__ a_s,
                                const float* __restrict__ a_d,
                                int n) {
    const float* X   = (SRCSEL == 0) ? Xparam : g_hfeat;
    float*       out = (DSTSEL == 0) ? g_hfeat : g_hlin;

    constexpr int COLS = FOUT / 32;   // 2 for FOUT=64, 1 for FOUT=32
    constexpr int RPT  = 4;           // rows per thread (ROWS = 32)
    constexpr int QF   = FIN / 4;

    __shared__ float Ws[FOUT * FIN];

    int t  = threadIdx.x;
    int r0 = blockIdx.x * 32;

    {
        const float4* W4 = (const float4*)W;
        for (int idx = t; idx < FOUT * QF; idx += 256) {
            int c = idx / QF, k4 = idx % QF;
            *(float4*)&Ws[c * FIN + 4 * (k4 ^ (c & 7))] = W4[idx];
        }
    }
    __syncthreads();

    int c  = t & 31;
    int rg = t >> 5;

    // clamped row base offsets (float4 units); clamp keeps OOB rows in-bounds,
    // their results are simply not written back.
    const float4* X4 = (const float4*)X;
    long rowoff[RPT];
#pragma unroll
    for (int i = 0; i < RPT; i++) {
        int gr = r0 + rg + 8 * i;
        rowoff[i] = (long)min(gr, n - 1) * QF;
    }

    float acc[RPT][COLS];
#pragma unroll
    for (int i = 0; i < RPT; i++)
#pragma unroll
        for (int j = 0; j < COLS; j++) acc[i][j] = 0.f;

#pragma unroll 4
    for (int k4 = 0; k4 < QF; k4++) {
        float4 xv[RPT];
#pragma unroll
        for (int i = 0; i < RPT; i++) xv[i] = X4[rowoff[i] + k4];   // broadcast LDG

        int ks = 4 * (k4 ^ (c & 7));
        float4 w0 = *(const float4*)&Ws[c * FIN + ks];
        float4 w1 = (COLS == 2) ? *(const float4*)&Ws[(c + 32) * FIN + ks]
                                : make_float4(0.f, 0.f, 0.f, 0.f);
#pragma unroll
        for (int i = 0; i < RPT; i++) {
            acc[i][0] = fmaf(xv[i].x, w0.x, acc[i][0]);
            acc[i][0] = fmaf(xv[i].y, w0.y, acc[i][0]);
            acc[i][0] = fmaf(xv[i].z, w0.z, acc[i][0]);
            acc[i][0] = fmaf(xv[i].w, w0.w, acc[i][0]);
            if (COLS == 2) {
                acc[i][1] = fmaf(xv[i].x, w1.x, acc[i][1]);
                acc[i][1] = fmaf(xv[i].y, w1.y, acc[i][1]);
                acc[i][1] = fmaf(xv[i].z, w1.z, acc[i][1]);
                acc[i][1] = fmaf(xv[i].w, w1.w, acc[i][1]);
            }
        }
    }

#pragma unroll
    for (int i = 0; i < RPT; i++) {
        int gr = r0 + rg + 8 * i;
        float v0 = acc[i][0];
        float v1 = (COLS == 2) ? acc[i][1] : 0.f;
        if (BIAS) {
            v0 += bias[c];
            if (COLS == 2) v1 += bias[c + 32];
        }
        if (gr < n) {
            out[gr * FOUT + c] = v0;
            if (COLS == 2) out[gr * FOUT + 32 + c] = v1;
        }
        if (COMPE) {
            float ps = v0 * a_s[c];
            float pd = v0 * a_d[c];
            if (COLS == 2) {
                ps += v1 * a_s[c + 32];
                pd += v1 * a_d[c + 32];
            }
            ps = gat_warp_sum(ps);
            pd = gat_warp_sum(pd);
            if (c == 0 && gr < n) {
                g_esrc[gr] = ps;
                g_edst[gr] = pd;
            }
        }
    }
}

// ---------------- warp-per-node softmax aggregation (FOUT=64) ---------------
// Fast path (deg <= 32, ~99.96% of nodes): the entire edge list lives in one
// register per lane. No g_ew traffic, no fence; pass 2 broadcasts sv/w via
// shfl (ALU) leaving ONE coalesced gather as the only memory op per edge.
// Fallback (deg > 32): g_ew two-pass.
// OUTSEL: 0 = g_hfeat, 1 = param out.
template <bool RELU, int OUTSEL>
__global__ void gat_agg64_kernel(const float* __restrict__ bias,
                                 float* __restrict__ outparam,
                                 int n) {
    const float2* h2 = (const float2*)g_hlin;
    float* out = (OUTSEL == 0) ? g_hfeat : outparam;

    int warp = (blockIdx.x * blockDim.x + threadIdx.x) >> 5;
    int lane = threadIdx.x & 31;
    if (warp >= n) return;

    int beg = g_off[warp];
    int deg = g_off[warp + 1] - beg;
    float ed = g_edst[warp];

    float ax = 0.f, ay = 0.f, s;

    if (deg <= 32) {
        int   sv_r = 0;
        float e    = -FLT_MAX;
        if (lane < deg) {
            sv_r = g_srcs[beg + lane];
            e = g_esrc[sv_r] + ed;
            e = (e > 0.f) ? e : 0.2f * e;
        }
        float m   = gat_warp_max(e);
        float w_r = (lane < deg) ? __expf(e - m) : 0.f;
        s = gat_warp_sum(w_r);

#pragma unroll 8
        for (int jj = 0; jj < deg; jj++) {
            int   sv = __shfl_sync(0xffffffffu, sv_r, jj);
            float wv = __shfl_sync(0xffffffffu, w_r, jj);
            float2 hv = h2[sv * 32 + lane];
            ax = fmaf(wv, hv.x, ax);
            ay = fmaf(wv, hv.y, ay);
        }
    } else {
        float lm = -FLT_MAX;
        for (int jj = lane; jj < deg; jj += 32) {
            int j  = beg + jj;
            int sv = g_srcs[j];
            float e = g_esrc[sv] + ed;
            e = (e > 0.f) ? e : 0.2f * e;
            g_ew[j] = e;
            lm = fmaxf(lm, e);
        }
        float m = gat_warp_max(lm);

        float ls = 0.f;
        for (int jj = lane; jj < deg; jj += 32) {
            int j = beg + jj;
            float wv = __expf(g_ew[j] - m);
            g_ew[j] = wv;
            ls += wv;
        }
        s = gat_warp_sum(ls);
        __threadfence_block();

#pragma unroll 4
        for (int jj = 0; jj < deg; jj++) {
            int   j  = beg + jj;
            int   sv = g_srcs[j];
            float wv = g_ew[j];
            float2 hv = h2[sv * 32 + lane];
            ax = fmaf(wv, hv.x, ax);
            ay = fmaf(wv, hv.y, ay);
        }
    }

    float inv = 1.f / s;                      // self-loop guarantees s > 0
    float2 bv = ((const float2*)bias)[lane];
    float rx = ax * inv + bv.x;
    float ry = ay * inv + bv.y;
    if (RELU) { rx = fmaxf(rx, 0.f); ry = fmaxf(ry, 0.f); }
    ((float2*)out)[warp * 32 + lane] = make_float2(rx, ry);
}

// ---------------- final agg (FOUT=32) + bias + L2 normalize -> out ----------
__global__ void gat_agg_final_kernel(const float* __restrict__ bias,
                                     float* __restrict__ out,
                                     int n) {
    const float* hlin = g_hlin;   // layer-3 hlin, stride 32

    int warp = (blockIdx.x * blockDim.x + threadIdx.x) >> 5;
    int lane = threadIdx.x & 31;
    if (warp >= n) return;

    int beg = g_off[warp];
    int deg = g_off[warp + 1] - beg;
    float ed = g_edst[warp];

    float a0 = 0.f, s;

    if (deg <= 32) {
        int   sv_r = 0;
        float e    = -FLT_MAX;
        if (lane < deg) {
            sv_r = g_srcs[beg + lane];
            e = g_esrc[sv_r] + ed;
            e = (e > 0.f) ? e : 0.2f * e;
        }
        float m   = gat_warp_max(e);
        float w_r = (lane < deg) ? __expf(e - m) : 0.f;
        s = gat_warp_sum(w_r);

#pragma unroll 8
        for (int jj = 0; jj < deg; jj++) {
            int   sv = __shfl_sync(0xffffffffu, sv_r, jj);
            float wv = __shfl_sync(0xffffffffu, w_r, jj);
            a0 = fmaf(wv, hlin[sv * 32 + lane], a0);
        }
    } else {
        float lm = -FLT_MAX;
        for (int jj = lane; jj < deg; jj += 32) {
            int j  = beg + jj;
            int sv = g_srcs[j];
            float e = g_esrc[sv] + ed;
            e = (e > 0.f) ? e : 0.2f * e;
            g_ew[j] = e;
            lm = fmaxf(lm, e);
        }
        float m = gat_warp_max(lm);

        float ls = 0.f;
        for (int jj = lane; jj < deg; jj += 32) {
            int j = beg + jj;
            float wv = __expf(g_ew[j] - m);
            g_ew[j] = wv;
            ls += wv;
        }
        s = gat_warp_sum(ls);
        __threadfence_block();

#pragma unroll 4
        for (int jj = 0; jj < deg; jj++) {
            int   j  = beg + jj;
            int   sv = g_srcs[j];
            float wv = g_ew[j];
            a0 = fmaf(wv, hlin[sv * 32 + lane], a0);
        }
    }

    float r0 = a0 / s + bias[lane];
    float ss  = gat_warp_sum(r0 * r0);
    float nrm = fmaxf(sqrtf(ss), 1e-12f);
    out[warp * 32 + lane] = r0 / nrm;
}

// ---------------- launch ----------------------------------------------------
extern "C" void kernel_launch(void* const* d_in, const int* in_sizes, int n_in,
                              void* d_out, int out_size) {
    const float* x    = (const float*)d_in[0];
    const int*   ei   = (const int*)d_in[1];     // int32 [2, E]
    const float* Wpre = (const float*)d_in[2];
    const float* bpre = (const float*)d_in[3];
    const float* W1   = (const float*)d_in[4];
    const float* a1s  = (const float*)d_in[5];
    const float* a1d  = (const float*)d_in[6];
    const float* b1   = (const float*)d_in[7];
    const float* W2   = (const float*)d_in[8];
    const float* a2s  = (const float*)d_in[9];
    const float* a2d  = (const float*)d_in[10];
    const float* b2   = (const float*)d_in[11];
    const float* W3   = (const float*)d_in[12];
    const float* a3s  = (const float*)d_in[13];
    const float* a3d  = (const float*)d_in[14];
    const float* b3   = (const float*)d_in[15];
    float*       out  = (float*)d_out;

    int N = in_sizes[0] / 128;
    int E = in_sizes[1] / 2;
    int ET = E + N;

    // ---- edge sort by dst (counting sort; hist zeroed by previous scan) ----
    gat_hist_kernel<<<(ET + 255) / 256, 256>>>(ei, E, N);
    gat_scan_kernel<<<1, 1024>>>(N);
    gat_scatter_kernel<<<(ET + 255) / 256, 256>>>(ei, E, N);

    int gemm_grid = (N + 31) / 32;
    int agg_grid  = (N + 7) / 8;   // 8 warps / block

    // ---- linear_pre: hfeat = x @ Wpre^T + bpre ----
    gat_gemm_kernel<128, 64, true, false, 0, 0><<<gemm_grid, 256>>>(
        x, Wpre, bpre, nullptr, nullptr, N);

    // ---- GAT layer 1 (relu): hlin = hfeat @ W1^T, agg -> hfeat ----
    gat_gemm_kernel<64, 64, false, true, 1, 1><<<gemm_grid, 256>>>(
        nullptr, W1, nullptr, a1s, a1d, N);
    gat_agg64_kernel<true, 0><<<agg_grid, 256>>>(b1, nullptr, N);

    // ---- GAT layer 2 (relu) ----
    gat_gemm_kernel<64, 64, false, true, 1, 1><<<gemm_grid, 256>>>(
        nullptr, W2, nullptr, a2s, a2d, N);
    gat_agg64_kernel<true, 0><<<agg_grid, 256>>>(b2, nullptr, N);

    // ---- GAT layer 3 (+ fused row L2-normalize) -> d_out ----
    gat_gemm_kernel<64, 32, false, true, 1, 1><<<gemm_grid, 256>>>(
        nullptr, W3, nullptr, a3s, a3d, N);
    gat_agg_final_kernel<<<agg_grid, 256>>>(b3, out, N);
}

// round 13
// speedup vs baseline: 1.0884x; 1.0884x over previous
#include <cuda_runtime.h>
#include <cuda_bf16.h>
#include <float.h>

// Problem-size upper bounds (from reference setup_inputs)
#define MAXN 50000
#define MAXE 800000
#define MAXET (MAXE + MAXN)   // + self loops

// ---------------- device scratch --------------------------------------------
__device__ float g_hfeat[MAXN * 64];
__device__ float g_hlin [MAXN * 64];
__device__ float g_esrc [MAXN];
__device__ float g_edst [MAXN];
__device__ float g_ew   [MAXET];
__device__ int   g_hist [MAXN];
__device__ int   g_off  [MAXN + 1];
__device__ int   g_cursor[MAXN];
__device__ int   g_srcs [MAXET];

// ---------------- helpers ---------------------------------------------------
__device__ __forceinline__ float gat_warp_sum(float v) {
#pragma unroll
    for (int o = 16; o; o >>= 1) v += __shfl_xor_sync(0xffffffffu, v, o);
    return v;
}
__device__ __forceinline__ float gat_warp_max(float v) {
#pragma unroll
    for (int o = 16; o; o >>= 1) v = fmaxf(v, __shfl_xor_sync(0xffffffffu, v, o));
    return v;
}

// ---------------- edge sorting (counting sort by dst) -----------------------
// edge_index is int32 [2, E] row-major: ei[i] = src, ei[E+i] = dst.
__global__ void gat_hist_kernel(const int* __restrict__ ei, int E, int n) {
    int i = blockIdx.x * blockDim.x + threadIdx.x;
    int total = E + n;
    if (i >= total) return;
    int d = (i < E) ? ei[E + i] : (i - E);
    if ((unsigned)d >= (unsigned)n) return;
    atomicAdd(&g_hist[d], 1);
}

// single-block scan; SELF-ZEROES g_hist after consuming it so the next graph
// replay starts from a clean histogram (first run relies on static zero-init).
__global__ void gat_scan_kernel(int n) {
    __shared__ int partial[1024];
    int t = threadIdx.x;
    int chunk = (n + 1023) / 1024;
    int begin = t * chunk;
    int endi  = min(begin + chunk, n);
    int sum = 0;
    for (int i = begin; i < endi; i++) sum += g_hist[i];
    partial[t] = sum;
    __syncthreads();
#pragma unroll
    for (int d = 1; d < 1024; d <<= 1) {
        int v = (t >= d) ? partial[t - d] : 0;
        __syncthreads();
        partial[t] += v;
        __syncthreads();
    }
    int run = (t == 0) ? 0 : partial[t - 1];
    for (int i = begin; i < endi; i++) {
        int h = g_hist[i];
        g_off[i]    = run;
        g_cursor[i] = run;
        run += h;
        g_hist[i] = 0;           // ready for next replay
    }
    if (t == 0) g_off[n] = partial[1023];
}

__global__ void gat_scatter_kernel(const int* __restrict__ ei, int E, int n) {
    int i = blockIdx.x * blockDim.x + threadIdx.x;
    int total = E + n;
    if (i >= total) return;
    int s, d;
    if (i < E) { s = ei[i]; d = ei[E + i]; }
    else       { s = d = i - E; }
    if ((unsigned)d >= (unsigned)n || (unsigned)s >= (unsigned)n) return;
    int pos = atomicAdd(&g_cursor[d], 1);
    g_srcs[pos] = s;
}

// ---------------- tiled GEMM with grid-stride tile loop ----------------------
// Block = 256 threads. W staged in smem ONCE per block (c-major, float4 XOR
// swizzle -> conflict-free), then the block loops over 32/64-row tiles,
// restaging only xs. This divides W L2 traffic + STS by ~tiles/block and
// removes the 1563-block tail.
// SRCSEL: 0 = param X, 1 = g_hfeat.   DSTSEL: 0 = g_hfeat, 1 = g_hlin.
template <int FIN, int FOUT, int ROWS, bool BIAS, bool COMPE, int SRCSEL, int DSTSEL>
__global__ void gat_gemm_kernel(const float* __restrict__ Xparam,
                                const float* __restrict__ W,
                                const float* __restrict__ bias,
                                const float* __restrict__ a_s,
                                const float* __restrict__ a_d,
                                int n) {
    const float* X   = (SRCSEL == 0) ? Xparam : g_hfeat;
    float*       out = (DSTSEL == 0) ? g_hfeat : g_hlin;

    constexpr int COLS = FOUT / 32;
    constexpr int RPT  = ROWS / 8;
    constexpr int QF   = FIN / 4;

    __shared__ float xs[ROWS * FIN];
    __shared__ float Ws[FOUT * FIN];

    int t = threadIdx.x;

    // W fill: once per block.
    {
        const float4* W4 = (const float4*)W;
        for (int idx = t; idx < FOUT * QF; idx += 256) {
            int c = idx / QF, k4 = idx % QF;
            *(float4*)&Ws[c * FIN + 4 * (k4 ^ (c & 7))] = W4[idx];
        }
    }

    int c  = t & 31;
    int rg = t >> 5;
    int ntiles = (n + ROWS - 1) / ROWS;

    for (int tile = blockIdx.x; tile < ntiles; tile += gridDim.x) {
        int r0 = tile * ROWS;
        __syncthreads();   // W ready (first iter) / xs WAR from previous tile
        {
            const float4* X4 = (const float4*)X;
            for (int idx = t; idx < ROWS * QF; idx += 256) {
                int row = idx / QF, q = idx % QF;
                int gr = r0 + row;
                float4 v = make_float4(0.f, 0.f, 0.f, 0.f);
                if (gr < n) v = X4[gr * QF + q];
                *(float4*)&xs[row * FIN + 4 * q] = v;
            }
        }
        __syncthreads();

        float acc[RPT][COLS];
#pragma unroll
        for (int i = 0; i < RPT; i++)
#pragma unroll
            for (int j = 0; j < COLS; j++) acc[i][j] = 0.f;

#pragma unroll 2
        for (int k4 = 0; k4 < QF; k4++) {
            int ks = 4 * (k4 ^ (c & 7));
            float4 w0 = *(const float4*)&Ws[c * FIN + ks];
            float4 w1 = (COLS == 2) ? *(const float4*)&Ws[(c + 32) * FIN + ks]
                                    : make_float4(0.f, 0.f, 0.f, 0.f);
#pragma unroll
            for (int i = 0; i < RPT; i++) {
                float4 xv = *(const float4*)&xs[(rg + 8 * i) * FIN + 4 * k4];
                acc[i][0] = fmaf(xv.x, w0.x, acc[i][0]);
                acc[i][0] = fmaf(xv.y, w0.y, acc[i][0]);
                acc[i][0] = fmaf(xv.z, w0.z, acc[i][0]);
                acc[i][0] = fmaf(xv.w, w0.w, acc[i][0]);
                if (COLS == 2) {
                    acc[i][1] = fmaf(xv.x, w1.x, acc[i][1]);
                    acc[i][1] = fmaf(xv.y, w1.y, acc[i][1]);
                    acc[i][1] = fmaf(xv.z, w1.z, acc[i][1]);
                    acc[i][1] = fmaf(xv.w, w1.w, acc[i][1]);
                }
            }
        }

#pragma unroll
        for (int i = 0; i < RPT; i++) {
            int row = rg + 8 * i;
            int gr  = r0 + row;
            float v0 = acc[i][0];
            float v1 = (COLS == 2) ? acc[i][1] : 0.f;
            if (BIAS) {
                v0 += bias[c];
                if (COLS == 2) v1 += bias[c + 32];
            }
            if (gr < n) {
                out[gr * FOUT + c] = v0;
                if (COLS == 2) out[gr * FOUT + 32 + c] = v1;
            }
            if (COMPE) {
                float ps = v0 * a_s[c];
                float pd = v0 * a_d[c];
                if (COLS == 2) {
                    ps += v1 * a_s[c + 32];
                    pd += v1 * a_d[c + 32];
                }
                ps = gat_warp_sum(ps);
                pd = gat_warp_sum(pd);
                if (c == 0 && gr < n) {
                    g_esrc[gr] = ps;
                    g_edst[gr] = pd;
                }
            }
        }
    }
}

// ---------------- warp-per-node softmax aggregation (FOUT=64) ---------------
// Fast path (deg <= 32, ~99.96% of nodes): edge list in one register per
// lane; pass 2 broadcasts sv/w via shfl, leaving ONE coalesced gather per
// edge. Fallback (deg > 32): g_ew two-pass.
// OUTSEL: 0 = g_hfeat, 1 = param out.
template <bool RELU, int OUTSEL>
__global__ void gat_agg64_kernel(const float* __restrict__ bias,
                                 float* __restrict__ outparam,
                                 int n) {
    const float2* h2 = (const float2*)g_hlin;
    float* out = (OUTSEL == 0) ? g_hfeat : outparam;

    int warp = (blockIdx.x * blockDim.x + threadIdx.x) >> 5;
    int lane = threadIdx.x & 31;
    if (warp >= n) return;

    int beg = g_off[warp];
    int deg = g_off[warp + 1] - beg;
    float ed = g_edst[warp];

    float ax = 0.f, ay = 0.f, s;

    if (deg <= 32) {
        int   sv_r = 0;
        float e    = -FLT_MAX;
        if (lane < deg) {
            sv_r = g_srcs[beg + lane];
            e = g_esrc[sv_r] + ed;
            e = (e > 0.f) ? e : 0.2f * e;
        }
        float m   = gat_warp_max(e);
        float w_r = (lane < deg) ? __expf(e - m) : 0.f;
        s = gat_warp_sum(w_r);

#pragma unroll 8
        for (int jj = 0; jj < deg; jj++) {
            int   sv = __shfl_sync(0xffffffffu, sv_r, jj);
            float wv = __shfl_sync(0xffffffffu, w_r, jj);
            float2 hv = h2[sv * 32 + lane];
            ax = fmaf(wv, hv.x, ax);
            ay = fmaf(wv, hv.y, ay);
        }
    } else {
        float lm = -FLT_MAX;
        for (int jj = lane; jj < deg; jj += 32) {
            int j  = beg + jj;
            int sv = g_srcs[j];
            float e = g_esrc[sv] + ed;
            e = (e > 0.f) ? e : 0.2f * e;
            g_ew[j] = e;
            lm = fmaxf(lm, e);
        }
        float m = gat_warp_max(lm);

        float ls = 0.f;
        for (int jj = lane; jj < deg; jj += 32) {
            int j = beg + jj;
            float wv = __expf(g_ew[j] - m);
            g_ew[j] = wv;
            ls += wv;
        }
        s = gat_warp_sum(ls);
        __threadfence_block();

#pragma unroll 4
        for (int jj = 0; jj < deg; jj++) {
            int   j  = beg + jj;
            int   sv = g_srcs[j];
            float wv = g_ew[j];
            float2 hv = h2[sv * 32 + lane];
            ax = fmaf(wv, hv.x, ax);
            ay = fmaf(wv, hv.y, ay);
        }
    }

    float inv = 1.f / s;                      // self-loop guarantees s > 0
    float2 bv = ((const float2*)bias)[lane];
    float rx = ax * inv + bv.x;
    float ry = ay * inv + bv.y;
    if (RELU) { rx = fmaxf(rx, 0.f); ry = fmaxf(ry, 0.f); }
    ((float2*)out)[warp * 32 + lane] = make_float2(rx, ry);
}

// ---------------- final agg (FOUT=32) + bias + L2 normalize -> out ----------
__global__ void gat_agg_final_kernel(const float* __restrict__ bias,
                                     float* __restrict__ out,
                                     int n) {
    const float* hlin = g_hlin;   // layer-3 hlin, stride 32

    int warp = (blockIdx.x * blockDim.x + threadIdx.x) >> 5;
    int lane = threadIdx.x & 31;
    if (warp >= n) return;

    int beg = g_off[warp];
    int deg = g_off[warp + 1] - beg;
    float ed = g_edst[warp];

    float a0 = 0.f, s;

    if (deg <= 32) {
        int   sv_r = 0;
        float e    = -FLT_MAX;
        if (lane < deg) {
            sv_r = g_srcs[beg + lane];
            e = g_esrc[sv_r] + ed;
            e = (e > 0.f) ? e : 0.2f * e;
        }
        float m   = gat_warp_max(e);
        float w_r = (lane < deg) ? __expf(e - m) : 0.f;
        s = gat_warp_sum(w_r);

#pragma unroll 8
        for (int jj = 0; jj < deg; jj++) {
            int   sv = __shfl_sync(0xffffffffu, sv_r, jj);
            float wv = __shfl_sync(0xffffffffu, w_r, jj);
            a0 = fmaf(wv, hlin[sv * 32 + lane], a0);
        }
    } else {
        float lm = -FLT_MAX;
        for (int jj = lane; jj < deg; jj += 32) {
            int j  = beg + jj;
            int sv = g_srcs[j];
            float e = g_esrc[sv] + ed;
            e = (e > 0.f) ? e : 0.2f * e;
            g_ew[j] = e;
            lm = fmaxf(lm, e);
        }
        float m = gat_warp_max(lm);

        float ls = 0.f;
        for (int jj = lane; jj < deg; jj += 32) {
            int j = beg + jj;
            float wv = __expf(g_ew[j] - m);
            g_ew[j] = wv;
            ls += wv;
        }
        s = gat_warp_sum(ls);
        __threadfence_block();

#pragma unroll 4
        for (int jj = 0; jj < deg; jj++) {
            int   j  = beg + jj;
            int   sv = g_srcs[j];
            float wv = g_ew[j];
            a0 = fmaf(wv, hlin[sv * 32 + lane], a0);
        }
    }

    float r0 = a0 / s + bias[lane];
    float ss  = gat_warp_sum(r0 * r0);
    float nrm = fmaxf(sqrtf(ss), 1e-12f);
    out[warp * 32 + lane] = r0 / nrm;
}

// ---------------- launch ----------------------------------------------------
extern "C" void kernel_launch(void* const* d_in, const int* in_sizes, int n_in,
                              void* d_out, int out_size) {
    const float* x    = (const float*)d_in[0];
    const int*   ei   = (const int*)d_in[1];     // int32 [2, E]
    const float* Wpre = (const float*)d_in[2];
    const float* bpre = (const float*)d_in[3];
    const float* W1   = (const float*)d_in[4];
    const float* a1s  = (const float*)d_in[5];
    const float* a1d  = (const float*)d_in[6];
    const float* b1   = (const float*)d_in[7];
    const float* W2   = (const float*)d_in[8];
    const float* a2s  = (const float*)d_in[9];
    const float* a2d  = (const float*)d_in[10];
    const float* b2   = (const float*)d_in[11];
    const float* W3   = (const float*)d_in[12];
    const float* a3s  = (const float*)d_in[13];
    const float* a3d  = (const float*)d_in[14];
    const float* b3   = (const float*)d_in[15];
    float*       out  = (float*)d_out;

    int N = in_sizes[0] / 128;
    int E = in_sizes[1] / 2;
    int ET = E + N;

    // ---- edge sort by dst (counting sort; hist zeroed by previous scan) ----
    gat_hist_kernel<<<(ET + 255) / 256, 256>>>(ei, E, N);
    gat_scan_kernel<<<1, 1024>>>(N);
    gat_scatter_kernel<<<(ET + 255) / 256, 256>>>(ei, E, N);

    int gemm_grid = 592;           // ~4 blocks/SM; grid-stride over tiles
    int agg_grid  = (N + 7) / 8;   // 8 warps / block

    // ---- linear_pre: hfeat = x @ Wpre^T + bpre (ROWS=32: 48KB smem) ----
    gat_gemm_kernel<128, 64, 32, true, false, 0, 0><<<gemm_grid, 256>>>(
        x, Wpre, bpre, nullptr, nullptr, N);

    // ---- GAT layer 1 (relu): hlin = hfeat @ W1^T, agg -> hfeat ----
    gat_gemm_kernel<64, 64, 64, false, true, 1, 1><<<gemm_grid, 256>>>(
        nullptr, W1, nullptr, a1s, a1d, N);
    gat_agg64_kernel<true, 0><<<agg_grid, 256>>>(b1, nullptr, N);

    // ---- GAT layer 2 (relu) ----
    gat_gemm_kernel<64, 64, 64, false, true, 1, 1><<<gemm_grid, 256>>>(
        nullptr, W2, nullptr, a2s, a2d, N);
    gat_agg64_kernel<true, 0><<<agg_grid, 256>>>(b2, nullptr, N);

    // ---- GAT layer 3 (+ fused row L2-normalize) -> d_out ----
    gat_gemm_kernel<64, 32, 64, false, true, 1, 1><<<gemm_grid, 256>>>(
        nullptr, W3, nullptr, a3s, a3d, N);
    gat_agg_final_kernel<<<agg_grid, 256>>>(b3, out, N);
}

// round 14
// speedup vs baseline: 1.1198x; 1.0289x over previous
#include <cuda_runtime.h>
#include <cuda_bf16.h>
#include <float.h>

// Problem-size upper bounds (from reference setup_inputs)
#define MAXN 50000
#define MAXE 800000
#define MAXET (MAXE + MAXN)   // + self loops

// ---------------- device scratch --------------------------------------------
__device__ float g_hfeat[MAXN * 64];
__device__ float g_hlin [MAXN * 64];
__device__ float g_esrc [MAXN];
__device__ float g_edst [MAXN];
__device__ float g_ew   [MAXET];
__device__ int   g_hist [MAXN];
__device__ int   g_off  [MAXN + 1];
__device__ int   g_cursor[MAXN];
__device__ int   g_srcs [MAXET];

// ---------------- helpers ---------------------------------------------------
__device__ __forceinline__ float gat_warp_sum(float v) {
#pragma unroll
    for (int o = 16; o; o >>= 1) v += __shfl_xor_sync(0xffffffffu, v, o);
    return v;
}
__device__ __forceinline__ float gat_warp_max(float v) {
#pragma unroll
    for (int o = 16; o; o >>= 1) v = fmaxf(v, __shfl_xor_sync(0xffffffffu, v, o));
    return v;
}

// ---------------- edge sorting (counting sort by dst) -----------------------
// edge_index is int32 [2, E] row-major: ei[i] = src, ei[E+i] = dst.
__global__ void gat_hist_kernel(const int* __restrict__ ei, int E, int n) {
    int i = blockIdx.x * blockDim.x + threadIdx.x;
    int total = E + n;
    if (i >= total) return;
    int d = (i < E) ? ei[E + i] : (i - E);
    if ((unsigned)d >= (unsigned)n) return;
    atomicAdd(&g_hist[d], 1);
}

// single-block scan; SELF-ZEROES g_hist after consuming it so the next graph
// replay starts from a clean histogram (first run relies on static zero-init).
__global__ void gat_scan_kernel(int n) {
    __shared__ int partial[1024];
    int t = threadIdx.x;
    int chunk = (n + 1023) / 1024;
    int begin = t * chunk;
    int endi  = min(begin + chunk, n);
    int sum = 0;
    for (int i = begin; i < endi; i++) sum += g_hist[i];
    partial[t] = sum;
    __syncthreads();
#pragma unroll
    for (int d = 1; d < 1024; d <<= 1) {
        int v = (t >= d) ? partial[t - d] : 0;
        __syncthreads();
        partial[t] += v;
        __syncthreads();
    }
    int run = (t == 0) ? 0 : partial[t - 1];
    for (int i = begin; i < endi; i++) {
        int h = g_hist[i];
        g_off[i]    = run;
        g_cursor[i] = run;
        run += h;
        g_hist[i] = 0;           // ready for next replay
    }
    if (t == 0) g_off[n] = partial[1023];
}

__global__ void gat_scatter_kernel(const int* __restrict__ ei, int E, int n) {
    int i = blockIdx.x * blockDim.x + threadIdx.x;
    int total = E + n;
    if (i >= total) return;
    int s, d;
    if (i < E) { s = ei[i]; d = ei[E + i]; }
    else       { s = d = i - E; }
    if ((unsigned)d >= (unsigned)n || (unsigned)s >= (unsigned)n) return;
    int pos = atomicAdd(&g_cursor[d], 1);
    g_srcs[pos] = s;
}

// ---------------- pre-GEMM: hfeat = x @ Wpre^T + bpre (FIN=128, K-split) ----
// ROWS=64 tile with K split into two 64-wide halves: xs holds full 128-wide
// rows (32KB), Ws holds one 16KB half of W, refilled between halves. Per
// k4-step: 2 Ws LDS.128 + 8 broadcast LDS per 64 FFMA (2x better LDS ratio
// than ROWS=32 full-K). 48KB smem -> 4 blocks/SM.
__global__ void gat_pregemm_kernel(const float* __restrict__ X,
                                   const float* __restrict__ W,
                                   const float* __restrict__ bias,
                                   int n) {
    constexpr int FIN = 128, ROWS = 64, KH = 64, QH = KH / 4;  // QH=16
    __shared__ float xs[ROWS * FIN];   // 32 KB
    __shared__ float Ws[64 * KH];      // 16 KB (one K-half of W[64][128])

    int t  = threadIdx.x;
    int c  = t & 31;
    int rg = t >> 5;
    int r0 = blockIdx.x * ROWS;

    // xs fill: full 128-wide rows, float4 coalesced
    {
        const float4* X4 = (const float4*)X;
        for (int idx = t; idx < ROWS * 32; idx += 256) {
            int row = idx >> 5, q = idx & 31;
            int gr = r0 + row;
            float4 v = make_float4(0.f, 0.f, 0.f, 0.f);
            if (gr < n) v = X4[gr * 32 + q];
            *(float4*)&xs[row * FIN + 4 * q] = v;
        }
    }

    float acc[8][2];
#pragma unroll
    for (int i = 0; i < 8; i++) { acc[i][0] = 0.f; acc[i][1] = 0.f; }

    const float4* W4 = (const float4*)W;   // W[64][128] row-major -> 32 f4/row
#pragma unroll
    for (int kh = 0; kh < 2; kh++) {
        __syncthreads();   // xs ready (first iter) / Ws WAR (second iter)
        for (int idx = t; idx < 64 * QH; idx += 256) {
            int cc = idx / QH, k4 = idx % QH;
            *(float4*)&Ws[cc * KH + 4 * (k4 ^ (cc & 7))] = W4[cc * 32 + kh * QH + k4];
        }
        __syncthreads();

#pragma unroll 2
        for (int k4 = 0; k4 < QH; k4++) {
            int ks = 4 * (k4 ^ (c & 7));
            float4 w0 = *(const float4*)&Ws[c * KH + ks];
            float4 w1 = *(const float4*)&Ws[(c + 32) * KH + ks];
#pragma unroll
            for (int i = 0; i < 8; i++) {
                float4 xv = *(const float4*)&xs[(rg + 8 * i) * FIN + kh * KH + 4 * k4];
                acc[i][0] = fmaf(xv.x, w0.x, acc[i][0]);
                acc[i][0] = fmaf(xv.y, w0.y, acc[i][0]);
                acc[i][0] = fmaf(xv.z, w0.z, acc[i][0]);
                acc[i][0] = fmaf(xv.w, w0.w, acc[i][0]);
                acc[i][1] = fmaf(xv.x, w1.x, acc[i][1]);
                acc[i][1] = fmaf(xv.y, w1.y, acc[i][1]);
                acc[i][1] = fmaf(xv.z, w1.z, acc[i][1]);
                acc[i][1] = fmaf(xv.w, w1.w, acc[i][1]);
            }
        }
    }

    float b0 = bias[c], b1 = bias[c + 32];
#pragma unroll
    for (int i = 0; i < 8; i++) {
        int gr = r0 + rg + 8 * i;
        if (gr < n) {
            g_hfeat[gr * 64 + c]      = acc[i][0] + b0;
            g_hfeat[gr * 64 + 32 + c] = acc[i][1] + b1;
        }
    }
}

// ---------------- tiled GEMM (FIN=64): out = X @ W^T, e_src/e_dst ------------
// Per-tile blocks (R10-proven). W c-major with float4 XOR swizzle.
// DSTSEL: 0 = g_hfeat, 1 = g_hlin.
template <int FOUT, int DSTSEL>
__global__ void gat_gemm64_kernel(const float* __restrict__ W,
                                  const float* __restrict__ a_s,
                                  const float* __restrict__ a_d,
                                  int n) {
    const float* X   = g_hfeat;
    float*       out = (DSTSEL == 0) ? g_hfeat : g_hlin;

    constexpr int FIN  = 64;
    constexpr int COLS = FOUT / 32;
    constexpr int ROWS = 64, RPT = 8;
    constexpr int QF   = FIN / 4;   // 16

    __shared__ float xs[ROWS * FIN];
    __shared__ float Ws[FOUT * FIN];

    int t  = threadIdx.x;
    int r0 = blockIdx.x * ROWS;

    {
        const float4* W4 = (const float4*)W;
        for (int idx = t; idx < FOUT * QF; idx += 256) {
            int c = idx / QF, k4 = idx % QF;
            *(float4*)&Ws[c * FIN + 4 * (k4 ^ (c & 7))] = W4[idx];
        }
    }
    {
        const float4* X4 = (const float4*)X;
        for (int idx = t; idx < ROWS * QF; idx += 256) {
            int row = idx / QF, q = idx % QF;
            int gr = r0 + row;
            float4 v = make_float4(0.f, 0.f, 0.f, 0.f);
            if (gr < n) v = X4[gr * QF + q];
            *(float4*)&xs[row * FIN + 4 * q] = v;
        }
    }
    __syncthreads();

    int c  = t & 31;
    int rg = t >> 5;

    float acc[RPT][COLS];
#pragma unroll
    for (int i = 0; i < RPT; i++)
#pragma unroll
        for (int j = 0; j < COLS; j++) acc[i][j] = 0.f;

#pragma unroll 2
    for (int k4 = 0; k4 < QF; k4++) {
        int ks = 4 * (k4 ^ (c & 7));
        float4 w0 = *(const float4*)&Ws[c * FIN + ks];
        float4 w1 = (COLS == 2) ? *(const float4*)&Ws[(c + 32) * FIN + ks]
                                : make_float4(0.f, 0.f, 0.f, 0.f);
#pragma unroll
        for (int i = 0; i < RPT; i++) {
            float4 xv = *(const float4*)&xs[(rg + 8 * i) * FIN + 4 * k4];
            acc[i][0] = fmaf(xv.x, w0.x, acc[i][0]);
            acc[i][0] = fmaf(xv.y, w0.y, acc[i][0]);
            acc[i][0] = fmaf(xv.z, w0.z, acc[i][0]);
            acc[i][0] = fmaf(xv.w, w0.w, acc[i][0]);
            if (COLS == 2) {
                acc[i][1] = fmaf(xv.x, w1.x, acc[i][1]);
                acc[i][1] = fmaf(xv.y, w1.y, acc[i][1]);
                acc[i][1] = fmaf(xv.z, w1.z, acc[i][1]);
                acc[i][1] = fmaf(xv.w, w1.w, acc[i][1]);
            }
        }
    }

#pragma unroll
    for (int i = 0; i < RPT; i++) {
        int gr = r0 + rg + 8 * i;
        float v0 = acc[i][0];
        float v1 = (COLS == 2) ? acc[i][1] : 0.f;
        if (gr < n) {
            out[gr * FOUT + c] = v0;
            if (COLS == 2) out[gr * FOUT + 32 + c] = v1;
        }
        float ps = v0 * a_s[c];
        float pd = v0 * a_d[c];
        if (COLS == 2) {
            ps += v1 * a_s[c + 32];
            pd += v1 * a_d[c + 32];
        }
        ps = gat_warp_sum(ps);
        pd = gat_warp_sum(pd);
        if (c == 0 && gr < n) {
            g_esrc[gr] = ps;
            g_edst[gr] = pd;
        }
    }
}

// ---------------- warp-per-node softmax aggregation (FOUT=64) ---------------
// Fast path (deg <= 32): edge list in one register per lane; pass 2
// broadcasts sv/w via shfl, ONE coalesced gather per edge. Fallback: g_ew.
// OUTSEL: 0 = g_hfeat, 1 = param out.
template <bool RELU, int OUTSEL>
__global__ void gat_agg64_kernel(const float* __restrict__ bias,
                                 float* __restrict__ outparam,
                                 int n) {
    const float2* h2 = (const float2*)g_hlin;
    float* out = (OUTSEL == 0) ? g_hfeat : outparam;

    int warp = (blockIdx.x * blockDim.x + threadIdx.x) >> 5;
    int lane = threadIdx.x & 31;
    if (warp >= n) return;

    int beg = g_off[warp];
    int deg = g_off[warp + 1] - beg;
    float ed = g_edst[warp];

    float ax = 0.f, ay = 0.f, s;

    if (deg <= 32) {
        int   sv_r = 0;
        float e    = -FLT_MAX;
        if (lane < deg) {
            sv_r = g_srcs[beg + lane];
            e = g_esrc[sv_r] + ed;
            e = (e > 0.f) ? e : 0.2f * e;
        }
        float m   = gat_warp_max(e);
        float w_r = (lane < deg) ? __expf(e - m) : 0.f;
        s = gat_warp_sum(w_r);

#pragma unroll 8
        for (int jj = 0; jj < deg; jj++) {
            int   sv = __shfl_sync(0xffffffffu, sv_r, jj);
            float wv = __shfl_sync(0xffffffffu, w_r, jj);
            float2 hv = h2[sv * 32 + lane];
            ax = fmaf(wv, hv.x, ax);
            ay = fmaf(wv, hv.y, ay);
        }
    } else {
        float lm = -FLT_MAX;
        for (int jj = lane; jj < deg; jj += 32) {
            int j  = beg + jj;
            int sv = g_srcs[j];
            float e = g_esrc[sv] + ed;
            e = (e > 0.f) ? e : 0.2f * e;
            g_ew[j] = e;
            lm = fmaxf(lm, e);
        }
        float m = gat_warp_max(lm);

        float ls = 0.f;
        for (int jj = lane; jj < deg; jj += 32) {
            int j = beg + jj;
            float wv = __expf(g_ew[j] - m);
            g_ew[j] = wv;
            ls += wv;
        }
        s = gat_warp_sum(ls);
        __threadfence_block();

#pragma unroll 4
        for (int jj = 0; jj < deg; jj++) {
            int   j  = beg + jj;
            int   sv = g_srcs[j];
            float wv = g_ew[j];
            float2 hv = h2[sv * 32 + lane];
            ax = fmaf(wv, hv.x, ax);
            ay = fmaf(wv, hv.y, ay);
        }
    }

    float inv = 1.f / s;                      // self-loop guarantees s > 0
    float2 bv = ((const float2*)bias)[lane];
    float rx = ax * inv + bv.x;
    float ry = ay * inv + bv.y;
    if (RELU) { rx = fmaxf(rx, 0.f); ry = fmaxf(ry, 0.f); }
    ((float2*)out)[warp * 32 + lane] = make_float2(rx, ry);
}

// ---------------- final agg (FOUT=32) + bias + L2 normalize -> out ----------
__global__ void gat_agg_final_kernel(const float* __restrict__ bias,
                                     float* __restrict__ out,
                                     int n) {
    const float* hlin = g_hlin;   // layer-3 hlin, stride 32

    int warp = (blockIdx.x * blockDim.x + threadIdx.x) >> 5;
    int lane = threadIdx.x & 31;
    if (warp >= n) return;

    int beg = g_off[warp];
    int deg = g_off[warp + 1] - beg;
    float ed = g_edst[warp];

    float a0 = 0.f, s;

    if (deg <= 32) {
        int   sv_r = 0;
        float e    = -FLT_MAX;
        if (lane < deg) {
            sv_r = g_srcs[beg + lane];
            e = g_esrc[sv_r] + ed;
            e = (e > 0.f) ? e : 0.2f * e;
        }
        float m   = gat_warp_max(e);
        float w_r = (lane < deg) ? __expf(e - m) : 0.f;
        s = gat_warp_sum(w_r);

#pragma unroll 8
        for (int jj = 0; jj < deg; jj++) {
            int   sv = __shfl_sync(0xffffffffu, sv_r, jj);
            float wv = __shfl_sync(0xffffffffu, w_r, jj);
            a0 = fmaf(wv, hlin[sv * 32 + lane], a0);
        }
    } else {
        float lm = -FLT_MAX;
        for (int jj = lane; jj < deg; jj += 32) {
            int j  = beg + jj;
            int sv = g_srcs[j];
            float e = g_esrc[sv] + ed;
            e = (e > 0.f) ? e : 0.2f * e;
            g_ew[j] = e;
            lm = fmaxf(lm, e);
        }
        float m = gat_warp_max(lm);

        float ls = 0.f;
        for (int jj = lane; jj < deg; jj += 32) {
            int j = beg + jj;
            float wv = __expf(g_ew[j] - m);
            g_ew[j] = wv;
            ls += wv;
        }
        s = gat_warp_sum(ls);
        __threadfence_block();

#pragma unroll 4
        for (int jj = 0; jj < deg; jj++) {
            int   j  = beg + jj;
            int   sv = g_srcs[j];
            float wv = g_ew[j];
            a0 = fmaf(wv, hlin[sv * 32 + lane], a0);
        }
    }

    float r0 = a0 / s + bias[lane];
    float ss  = gat_warp_sum(r0 * r0);
    float nrm = fmaxf(sqrtf(ss), 1e-12f);
    out[warp * 32 + lane] = r0 / nrm;
}

// ---------------- launch ----------------------------------------------------
extern "C" void kernel_launch(void* const* d_in, const int* in_sizes, int n_in,
                              void* d_out, int out_size) {
    const float* x    = (const float*)d_in[0];
    const int*   ei   = (const int*)d_in[1];     // int32 [2, E]
    const float* Wpre = (const float*)d_in[2];
    const float* bpre = (const float*)d_in[3];
    const float* W1   = (const float*)d_in[4];
    const float* a1s  = (const float*)d_in[5];
    const float* a1d  = (const float*)d_in[6];
    const float* b1   = (const float*)d_in[7];
    const float* W2   = (const float*)d_in[8];
    const float* a2s  = (const float*)d_in[9];
    const float* a2d  = (const float*)d_in[10];
    const float* b2   = (const float*)d_in[11];
    const float* W3   = (const float*)d_in[12];
    const float* a3s  = (const float*)d_in[13];
    const float* a3d  = (const float*)d_in[14];
    const float* b3   = (const float*)d_in[15];
    float*       out  = (float*)d_out;

    int N = in_sizes[0] / 128;
    int E = in_sizes[1] / 2;
    int ET = E + N;

    // ---- edge sort by dst (counting sort; hist zeroed by previous scan) ----
    gat_hist_kernel<<<(ET + 255) / 256, 256>>>(ei, E, N);
    gat_scan_kernel<<<1, 1024>>>(N);
    gat_scatter_kernel<<<(ET + 255) / 256, 256>>>(ei, E, N);

    int tile64_grid = (N + 63) / 64;
    int agg_grid    = (N + 7) / 8;   // 8 warps / block

    // ---- linear_pre: hfeat = x @ Wpre^T + bpre (K-split, ROWS=64) ----
    gat_pregemm_kernel<<<tile64_grid, 256>>>(x, Wpre, bpre, N);

    // ---- GAT layer 1 (relu): hlin = hfeat @ W1^T, agg -> hfeat ----
    gat_gemm64_kernel<64, 1><<<tile64_grid, 256>>>(W1, a1s, a1d, N);
    gat_agg64_kernel<true, 0><<<agg_grid, 256>>>(b1, nullptr, N);

    // ---- GAT layer 2 (relu) ----
    gat_gemm64_kernel<64, 1><<<tile64_grid, 256>>>(W2, a2s, a2d, N);
    gat_agg64_kernel<true, 0><<<agg_grid, 256>>>(b2, nullptr, N);

    // ---- GAT layer 3 (+ fused row L2-normalize) -> d_out ----
    gat_gemm64_kernel<32, 1><<<tile64_grid, 256>>>(W3, a3s, a3d, N);
    gat_agg_final_kernel<<<agg_grid, 256>>>(b3, out, N);
}